// round 8
// baseline (speedup 1.0000x reference)
#include <cuda_runtime.h>
#include <cstdint>

// SimplePatchScorer: out[b, j] = dot(W, permuted_patch_row(b, j)) + bias
//   x: (512, 3, 224, 224) fp32, W: (1,768), b: (1,) -> out: (512, 196)
//
// flat[u], u = s*588 + v; s = ph*16+pw; v = c*196 + hn*14 + wn.
// out[b,j] = sum_t W[t]*flat[768j+t] + bias.
// lcm(588,768)=37632 => 4 groups/image: s in [64g,64g+64), j in [49g,49g+49).
//
// v6: eighth-tiles (8 s' rows: ph = 4g + h/2, pw-half = h&1) each covering
// contiguous u' range [4704h, 4704h+4704). cp.async (4B) scatters gmem ->
// transposed smem tile with zero register staging; DOUBLE BUFFERED so tile
// h+1 streams from DRAM while tile h is computed. 2x(8x604)+W ~= 41.8 KB
// -> 5 CTAs/SM. Phase 2: conflict-free float4 LDS dot, register accums.

#define VPAD    604
#define TILE_U  4704           // 8 * 588
#define THREADS 256

__device__ __forceinline__ void cp_async4(uint32_t dst, const float* src) {
    asm volatile("cp.async.ca.shared.global [%0], [%1], 4;" :: "r"(dst), "l"(src));
}
__device__ __forceinline__ void cp_commit() {
    asm volatile("cp.async.commit_group;" ::: "memory");
}
template <int N>
__device__ __forceinline__ void cp_wait() {
    asm volatile("cp.async.wait_group %0;" :: "n"(N) : "memory");
}

__global__ __launch_bounds__(THREADS, 5)
void patch_scorer_v6(const float* __restrict__ x,
                     const float* __restrict__ W,
                     const float* __restrict__ bias,
                     float* __restrict__ out)
{
    extern __shared__ float smem[];
    float* Y0 = smem;                    // [8][604]
    float* Y1 = smem + 8 * VPAD;         // [8][604]
    float* Ws = smem + 16 * VPAD;        // [768]

    const int tid  = threadIdx.x;
    const int g    = blockIdx.x & 3;
    const int b    = blockIdx.x >> 2;
    const int lane = tid & 31;
    const int warp = tid >> 5;           // 8 warps

    const float* xb = x + (size_t)b * (3 * 224 * 224);
    const uint32_t ybase0 = (uint32_t)__cvta_generic_to_shared(Y0);
    const uint32_t ybase1 = (uint32_t)__cvta_generic_to_shared(Y1);

    if (tid < 192)                       // 192 float4 = 768 floats
        ((float4*)Ws)[tid] = ((const float4*)W)[tid];
    // visible after the first __syncthreads below

    // per-thread initial decode for the tile-load loop (same every tile):
    // float4 index f = tid: k = f&1, r = f>>1, wn = r%14, hn = (r/14)%14, c = r/196
    const int k0  = tid & 1;
    const int r0  = tid >> 1;
    const int wn0 = r0 % 14;
    const int t0  = r0 / 14;
    const int hn0 = t0 % 14;
    const int c0  = t0 / 14;

    // ---- tile loader: issue all cp.asyncs for tile h into buffer ybase ----
    auto issue_tile = [&](int h, uint32_t ybase) {
        const int half = h & 1;
        const int ph   = 4 * g + (h >> 1);
        int k = k0, wn = wn0, hn = hn0, c = c0;
        #pragma unroll 5
        for (int f = tid; f < 1176; f += THREADS) {
            const float* src = xb + (size_t)c * 50176 + (hn * 16 + ph) * 224
                             + 16 * wn + 8 * half + 4 * k;
            uint32_t dst = ybase + (uint32_t)(((k << 2)) * VPAD
                             + c * 196 + hn * 14 + wn) * 4u;
            cp_async4(dst + 0 * VPAD * 4, src + 0);
            cp_async4(dst + 1 * VPAD * 4, src + 1);
            cp_async4(dst + 2 * VPAD * 4, src + 2);
            cp_async4(dst + 3 * VPAD * 4, src + 3);
            // f += 256: k unchanged (256 even), r += 128 => wn+=2, hn+=9, carries
            wn += 2; hn += 9;
            if (wn >= 14) { wn -= 14; hn++; }
            if (hn >= 14) { hn -= 14; c++; }
        }
        cp_commit();
    };

    float acc[7];
    #pragma unroll
    for (int i = 0; i < 7; i++) acc[i] = 0.f;

    issue_tile(0, ybase0);

    for (int h = 0; h < 8; h++) {
        const float* Yt = (h & 1) ? Y1 : Y0;
        if (h + 1 < 8) {
            issue_tile(h + 1, (h + 1) & 1 ? ybase1 : ybase0);
            cp_wait<1>();                // tile h landed
        } else {
            cp_wait<0>();
        }
        __syncthreads();                 // tile h visible to all threads

        // ---- compute: vectorized dot over u' in [4704h, 4704h+4704) ----
        const int rlo = TILE_U * h, rhi = rlo + TILE_U;
        const int sp0 = 8 * h;           // first s' row of this tile
        #pragma unroll
        for (int i = 0; i < 7; i++) {
            int jl = warp + 8 * i;
            if (jl < 49) {
                int ulo = max(768 * jl, rlo);
                int uhi = min(768 * jl + 768, rhi);
                int u   = ulo + 4 * lane;
                if (u < uhi) {
                    int sp = (unsigned)u / 588u;        // one div per segment
                    int v  = u - sp * 588;
                    int yo = (sp - sp0) * VPAD + v;
                    int wo = u - 768 * jl;
                    float a = 0.f;
                    while (u < uhi) {
                        float4 yv = *(const float4*)&Yt[yo];
                        float4 wv = *(const float4*)&Ws[wo];
                        a = fmaf(wv.x, yv.x, a);
                        a = fmaf(wv.y, yv.y, a);
                        a = fmaf(wv.z, yv.z, a);
                        a = fmaf(wv.w, yv.w, a);
                        u  += 128;                      // 32 lanes * 4 floats
                        wo += 128;
                        v  += 128;
                        yo += 128;
                        if (v >= 588) { v -= 588; yo += VPAD - 588; }
                    }
                    acc[i] += a;
                }
            }
        }
        __syncthreads();                 // compute h done before tile h+2 reuses buffer
    }

    // ---- final warp reductions + store ----
    const float bv = __ldg(bias);
    #pragma unroll
    for (int i = 0; i < 7; i++) {
        int jl = warp + 8 * i;
        if (jl < 49) {
            float a = acc[i];
            #pragma unroll
            for (int off = 16; off; off >>= 1)
                a += __shfl_xor_sync(0xffffffffu, a, off);
            if (lane == 0)
                out[b * 196 + 49 * g + jl] = a + bv;
        }
    }
}

extern "C" void kernel_launch(void* const* d_in, const int* in_sizes, int n_in,
                              void* d_out, int out_size)
{
    const float* x  = (const float*)d_in[0];
    const float* W  = (const float*)d_in[1];
    const float* bb = (const float*)d_in[2];
    float* out = (float*)d_out;

    const int smem_bytes = (16 * VPAD + 768) * sizeof(float);  // ~41.8 KB
    cudaFuncSetAttribute(patch_scorer_v6,
                         cudaFuncAttributeMaxDynamicSharedMemorySize, smem_bytes);

    patch_scorer_v6<<<512 * 4, THREADS, smem_bytes>>>(x, W, bb, out);
}